// round 1
// baseline (speedup 1.0000x reference)
#include <cuda_runtime.h>
#include <math.h>

#define B_    32
#define CIN   3
#define HIN   224
#define WIN   224
#define CO    192
#define OH    112
#define OW    112
#define PH    56
#define PW    56
#define NPC   (B_*OH*OW)   // elements per channel for BN stats = 401408

// -------- device scratch (allocation-free rule: __device__ globals) --------
__device__ float g_y[(size_t)B_*CO*OH*OW];   // conv output, ~294 MB
__device__ float g_sum[CO];
__device__ float g_sq[CO];
__device__ float g_scale[CO];
__device__ float g_shift[CO];

// ---------------------------------------------------------------------------
__global__ void zero_stats_kernel() {
    int t = threadIdx.x;
    if (t < CO) { g_sum[t] = 0.f; g_sq[t] = 0.f; }
}

// ---------------------------------------------------------------------------
// Conv kernel: grid (14 oy-tiles, 32 batch, 6 cgroups of 32ch), 224 threads.
// Each thread: 4 output cols x 4 channels x 8 output rows.
// smem: input tile 3ch x 17rows x 228cols + weights 27x32 + 64 reduce slots.
#define CONV_THREADS 224
#define IN_ROWS 17
#define IN_COLS 228
#define SIN_SZ  (CIN*IN_ROWS*IN_COLS)   // 11628
#define SW_SZ   (27*32)                 // 864

__global__ __launch_bounds__(CONV_THREADS)
void conv_stats_kernel(const float* __restrict__ x,
                       const float* __restrict__ conv_w,
                       const float* __restrict__ conv_b) {
    extern __shared__ float smem[];
    float* sIn  = smem;                  // [ci][row][col]
    float* sW   = smem + SIN_SZ;         // [tap][c_local 0..31]
    float* sSum = smem + SIN_SZ + SW_SZ; // [32]
    float* sSq  = sSum + 32;             // [32]

    const int tid = threadIdx.x;
    const int oy0 = blockIdx.x * 8;
    const int b   = blockIdx.y;
    const int cz  = blockIdx.z;          // channel group (32 ch)

    const int oxg = tid % 28;            // 28 groups of 4 cols = 112
    const int cg  = tid / 28;            // 8 groups of 4 ch = 32
    const int ox0 = oxg * 4;

    if (tid < 64) { sSum[tid & 31] = 0.f; sSq[tid & 31] = 0.f; } // both arrays: tid<32 -> sSum, 32..63 -> sSq
    if (tid < 32) sSum[tid] = 0.f; else if (tid < 64) sSq[tid-32] = 0.f;

    // load input tile (zero-padded)
    const int row_base = 2*oy0 - 1;
    for (int idx = tid; idx < SIN_SZ; idx += CONV_THREADS) {
        int ci  = idx / (IN_ROWS*IN_COLS);
        int rem = idx % (IN_ROWS*IN_COLS);
        int r   = rem / IN_COLS;
        int col = rem % IN_COLS;
        int gr = row_base + r;
        int gc = col - 1;
        float v = 0.f;
        if (gr >= 0 && gr < HIN && gc >= 0 && gc < WIN)
            v = x[((size_t)(b*CIN + ci)*HIN + gr)*WIN + gc];
        sIn[idx] = v;
    }
    // load weights for this channel group: sW[tap*32 + cl]
    for (int idx = tid; idx < SW_SZ; idx += CONV_THREADS) {
        int tap = idx / 32;
        int cl  = idx % 32;
        sW[idx] = conv_w[(cz*32 + cl)*27 + tap];
    }
    __syncthreads();

    const int cbase = cz*32 + cg*4;
    float bias0 = conv_b[cbase+0];
    float bias1 = conv_b[cbase+1];
    float bias2 = conv_b[cbase+2];
    float bias3 = conv_b[cbase+3];

    float lsum[4] = {0.f,0.f,0.f,0.f};
    float lsq [4] = {0.f,0.f,0.f,0.f};

    #pragma unroll 1
    for (int oy = 0; oy < 8; ++oy) {
        float acc[4][4];
        #pragma unroll
        for (int p = 0; p < 4; ++p) {
            acc[0][p] = bias0; acc[1][p] = bias1;
            acc[2][p] = bias2; acc[3][p] = bias3;
        }
        #pragma unroll
        for (int ci = 0; ci < 3; ++ci) {
            #pragma unroll
            for (int ky = 0; ky < 3; ++ky) {
                const int r = 2*oy + ky;
                const float* ip = &sIn[ci*IN_ROWS*IN_COLS + r*IN_COLS + 8*oxg];
                float4 va = *(const float4*)(ip);
                float4 vb = *(const float4*)(ip + 4);
                float  v8 = ip[8];
                float v[9] = {va.x,va.y,va.z,va.w, vb.x,vb.y,vb.z,vb.w, v8};
                #pragma unroll
                for (int kx = 0; kx < 3; ++kx) {
                    float4 w = *(const float4*)&sW[(ci*9 + ky*3 + kx)*32 + cg*4];
                    #pragma unroll
                    for (int p = 0; p < 4; ++p) {
                        float xv = v[2*p + kx];
                        acc[0][p] = fmaf(w.x, xv, acc[0][p]);
                        acc[1][p] = fmaf(w.y, xv, acc[1][p]);
                        acc[2][p] = fmaf(w.z, xv, acc[2][p]);
                        acc[3][p] = fmaf(w.w, xv, acc[3][p]);
                    }
                }
            }
        }
        const int OY = oy0 + oy;
        #pragma unroll
        for (int c = 0; c < 4; ++c) {
            float4 o = make_float4(acc[c][0], acc[c][1], acc[c][2], acc[c][3]);
            *(float4*)&g_y[((size_t)(b*CO + cbase + c)*OH + OY)*OW + ox0] = o;
            lsum[c] += o.x + o.y + o.z + o.w;
            lsq [c] += o.x*o.x + o.y*o.y + o.z*o.z + o.w*o.w;
        }
    }

    #pragma unroll
    for (int c = 0; c < 4; ++c) {
        atomicAdd(&sSum[cg*4 + c], lsum[c]);
        atomicAdd(&sSq [cg*4 + c], lsq [c]);
    }
    __syncthreads();
    if (tid < 32) {
        atomicAdd(&g_sum[cz*32 + tid], sSum[tid]);
        atomicAdd(&g_sq [cz*32 + tid], sSq [tid]);
    }
}

// ---------------------------------------------------------------------------
__global__ void finalize_stats_kernel(const float* __restrict__ gamma,
                                      const float* __restrict__ beta) {
    int c = threadIdx.x;
    if (c >= CO) return;
    float invN  = 1.0f / (float)NPC;
    float mean  = g_sum[c] * invN;
    float var   = g_sq[c] * invN - mean*mean;
    float inv   = rsqrtf(var + 1e-5f);
    float scale = gamma[c] * inv;
    g_scale[c]  = scale;
    g_shift[c]  = beta[c] - mean*scale;
}

// ---------------------------------------------------------------------------
// BN + GELU + MaxPool: one block per (c,b) plane. smem holds gelu(plane).
#define POOL_THREADS 256
#define PLANE (OH*OW)   // 12544

__global__ __launch_bounds__(POOL_THREADS)
void bn_gelu_pool_kernel(float* __restrict__ out) {
    extern __shared__ float sG[];   // [112*112]
    const int c = blockIdx.x;
    const int b = blockIdx.y;
    const int tid = threadIdx.x;

    const float scale = g_scale[c];
    const float shift = g_shift[c];
    const float4* base4 = (const float4*)&g_y[(size_t)(b*CO + c)*PLANE];
    float4* s4 = (float4*)sG;

    for (int i = tid; i < PLANE/4; i += POOL_THREADS) {
        float4 v = base4[i];
        float a0 = v.x*scale + shift;
        float a1 = v.y*scale + shift;
        float a2 = v.z*scale + shift;
        float a3 = v.w*scale + shift;
        v.x = 0.5f*a0*(1.0f + erff(a0*0.70710678118654752f));
        v.y = 0.5f*a1*(1.0f + erff(a1*0.70710678118654752f));
        v.z = 0.5f*a2*(1.0f + erff(a2*0.70710678118654752f));
        v.w = 0.5f*a3*(1.0f + erff(a3*0.70710678118654752f));
        s4[i] = v;
    }
    __syncthreads();

    float* op = &out[((size_t)(b*CO + c)*PH)*PW];
    for (int i = tid; i < PH*PW; i += POOL_THREADS) {
        int py = i / PW;
        int px = i % PW;
        float m = -3.4e38f;
        #pragma unroll
        for (int ky = 0; ky < 3; ++ky) {
            int r = 2*py - 1 + ky;
            if (r < 0 || r >= OH) continue;
            #pragma unroll
            for (int kx = 0; kx < 3; ++kx) {
                int cc = 2*px - 1 + kx;
                if (cc < 0 || cc >= OW) continue;
                m = fmaxf(m, sG[r*OW + cc]);
            }
        }
        op[i] = m;
    }
}

// ---------------------------------------------------------------------------
extern "C" void kernel_launch(void* const* d_in, const int* in_sizes, int n_in,
                              void* d_out, int out_size) {
    const float* x      = (const float*)d_in[0];
    const float* conv_w = (const float*)d_in[1];
    const float* conv_b = (const float*)d_in[2];
    const float* gamma  = (const float*)d_in[3];
    const float* beta   = (const float*)d_in[4];
    float* out = (float*)d_out;

    const int conv_smem = (SIN_SZ + SW_SZ + 64) * sizeof(float);   // 50224 B
    const int pool_smem = PLANE * sizeof(float);                    // 50176 B
    cudaFuncSetAttribute(conv_stats_kernel,
                         cudaFuncAttributeMaxDynamicSharedMemorySize, conv_smem);
    cudaFuncSetAttribute(bn_gelu_pool_kernel,
                         cudaFuncAttributeMaxDynamicSharedMemorySize, pool_smem);

    zero_stats_kernel<<<1, CO>>>();
    conv_stats_kernel<<<dim3(14, B_, 6), CONV_THREADS, conv_smem>>>(x, conv_w, conv_b);
    finalize_stats_kernel<<<1, CO>>>(gamma, beta);
    bn_gelu_pool_kernel<<<dim3(CO, B_), POOL_THREADS, pool_smem>>>(out);
}

// round 2
// speedup vs baseline: 1.4922x; 1.4922x over previous
#include <cuda_runtime.h>
#include <cuda_fp16.h>
#include <math.h>

#define B_    32
#define CIN   3
#define HIN   224
#define WIN   224
#define CO    192
#define OH    112
#define OW    112
#define PH    56
#define PW    56
#define NPC   (B_*OH*OW)   // 401408

// -------- device scratch (__device__ globals; no allocations allowed) ------
__device__ __half g_yh[(size_t)B_*CO*OH*OW];   // conv output fp16, ~154 MB
__device__ float g_sum[CO];
__device__ float g_sq[CO];
__device__ float g_scale[CO];
__device__ float g_shift[CO];

// ---------------------------------------------------------------------------
__global__ void zero_stats_kernel() {
    int t = threadIdx.x;
    if (t < CO) { g_sum[t] = 0.f; g_sq[t] = 0.f; }
}

// ---------------------------------------------------------------------------
// Conv + stats.
//  Block: 256 threads = 8 warps. Warp w -> 8 channels (warp-uniform weights ->
//  broadcast LDS, N=1). Lane L -> 2 adjacent output cols (16B input stride ->
//  conflict-free LDS.128). Each thread: 8 ch x 2 cols x 8 rows.
//  Grid: (2 col-tiles x 14 row-tiles, 32 batch, 3 groups of 64 ch).
#define CONV_THREADS 256
#define IN_ROWS  17
#define IN_COLS  132                     // covers 129 needed, 16B-aligned rows
#define SIN_SZ   (CIN*IN_ROWS*IN_COLS)   // 6732 floats
#define SW_SZ    (27*64)                 // 1728 floats

__global__ __launch_bounds__(CONV_THREADS)
void conv_stats_kernel(const float* __restrict__ x,
                       const float* __restrict__ conv_w,
                       const float* __restrict__ conv_b) {
    extern __shared__ float smem[];
    float* sIn = smem;              // [ci][17][132]
    float* sW  = smem + SIN_SZ;     // [tap][ch_local 0..63]

    const int tid  = threadIdx.x;
    const int lane = tid & 31;
    const int wrp  = tid >> 5;

    const int ct = blockIdx.x & 1;       // col tile (0: cols 0-63, 1: 64-111)
    const int rt = blockIdx.x >> 1;      // row tile (8 rows each)
    const int b  = blockIdx.y;
    const int cz = blockIdx.z;           // 64-channel group

    const int c0    = ct * 64;
    const int ncols = ct ? 48 : 64;
    const bool active = (2*lane) < ncols;

    // ---- load input tile (zero padded) ----
    const int rowbase = 16*rt - 1;
    const int colbase = 2*c0 - 1;
    for (int idx = tid; idx < SIN_SZ; idx += CONV_THREADS) {
        int ci  = idx / (IN_ROWS*IN_COLS);
        int rem = idx - ci*(IN_ROWS*IN_COLS);
        int r   = rem / IN_COLS;
        int col = rem - r*IN_COLS;
        int gr = rowbase + r;
        int gc = colbase + col;
        float v = 0.f;
        if (gr >= 0 && gr < HIN && gc >= 0 && gc < WIN)
            v = x[((size_t)(b*CIN + ci)*HIN + gr)*WIN + gc];
        sIn[idx] = v;
    }
    // ---- load weights: sW[tap*64 + cl] ----
    for (int idx = tid; idx < SW_SZ; idx += CONV_THREADS) {
        int tap = idx >> 6;
        int cl  = idx & 63;
        sW[idx] = conv_w[(cz*64 + cl)*27 + tap];
    }
    __syncthreads();

    const int cbase = cz*64 + wrp*8;
    float bias[8];
    #pragma unroll
    for (int c = 0; c < 8; ++c) bias[c] = conv_b[cbase + c];

    float lsum[8], lsq[8];
    #pragma unroll
    for (int c = 0; c < 8; ++c) { lsum[c] = 0.f; lsq[c] = 0.f; }

    const float4* sW4 = (const float4*)sW;

    #pragma unroll 1
    for (int oy = 0; oy < 8; ++oy) {
        float acc[8][2];
        #pragma unroll
        for (int c = 0; c < 8; ++c) { acc[c][0] = bias[c]; acc[c][1] = bias[c]; }

        #pragma unroll
        for (int ci = 0; ci < 3; ++ci) {
            #pragma unroll
            for (int ky = 0; ky < 3; ++ky) {
                const int r = 2*oy + ky;
                const float* ip = &sIn[ci*(IN_ROWS*IN_COLS) + r*IN_COLS + 4*lane];
                float4 a = *(const float4*)ip;     // conflict-free: 16B/lane
                float  e = ip[4];
                float xs0[3] = {a.x, a.y, a.z};    // out col 2L
                float xs1[3] = {a.z, a.w, e};      // out col 2L+1
                #pragma unroll
                for (int kx = 0; kx < 3; ++kx) {
                    const int tap = ci*9 + ky*3 + kx;
                    float4 w0 = sW4[tap*16 + wrp*2 + 0];   // ch 0-3 (uniform)
                    float4 w1 = sW4[tap*16 + wrp*2 + 1];   // ch 4-7 (uniform)
                    float x0 = xs0[kx], x1 = xs1[kx];
                    acc[0][0] = fmaf(w0.x, x0, acc[0][0]); acc[0][1] = fmaf(w0.x, x1, acc[0][1]);
                    acc[1][0] = fmaf(w0.y, x0, acc[1][0]); acc[1][1] = fmaf(w0.y, x1, acc[1][1]);
                    acc[2][0] = fmaf(w0.z, x0, acc[2][0]); acc[2][1] = fmaf(w0.z, x1, acc[2][1]);
                    acc[3][0] = fmaf(w0.w, x0, acc[3][0]); acc[3][1] = fmaf(w0.w, x1, acc[3][1]);
                    acc[4][0] = fmaf(w1.x, x0, acc[4][0]); acc[4][1] = fmaf(w1.x, x1, acc[4][1]);
                    acc[5][0] = fmaf(w1.y, x0, acc[5][0]); acc[5][1] = fmaf(w1.y, x1, acc[5][1]);
                    acc[6][0] = fmaf(w1.z, x0, acc[6][0]); acc[6][1] = fmaf(w1.z, x1, acc[6][1]);
                    acc[7][0] = fmaf(w1.w, x0, acc[7][0]); acc[7][1] = fmaf(w1.w, x1, acc[7][1]);
                }
            }
        }

        if (active) {
            const int OY = 8*rt + oy;
            #pragma unroll
            for (int c = 0; c < 8; ++c) {
                lsum[c] += acc[c][0] + acc[c][1];
                lsq [c] += acc[c][0]*acc[c][0] + acc[c][1]*acc[c][1];
                __half2* dst = (__half2*)(g_yh + ((size_t)(b*CO + cbase + c)*OH + OY)*OW);
                dst[(c0 >> 1) + lane] = __floats2half2_rn(acc[c][0], acc[c][1]);
            }
        }
    }

    // warp-reduce stats, lane0 atomics (per-warp channels are unique)
    #pragma unroll
    for (int c = 0; c < 8; ++c) {
        float s = lsum[c], q = lsq[c];
        #pragma unroll
        for (int o = 16; o > 0; o >>= 1) {
            s += __shfl_xor_sync(0xffffffffu, s, o);
            q += __shfl_xor_sync(0xffffffffu, q, o);
        }
        if (lane == 0) {
            atomicAdd(&g_sum[cbase + c], s);
            atomicAdd(&g_sq [cbase + c], q);
        }
    }
}

// ---------------------------------------------------------------------------
__global__ void finalize_stats_kernel(const float* __restrict__ gamma,
                                      const float* __restrict__ beta) {
    int c = threadIdx.x;
    if (c >= CO) return;
    float invN  = 1.0f / (float)NPC;
    float mean  = g_sum[c] * invN;
    float var   = g_sq[c] * invN - mean*mean;
    float inv   = rsqrtf(var + 1e-5f);
    float scale = gamma[c] * inv;
    g_scale[c]  = scale;
    g_shift[c]  = beta[c] - mean*scale;
}

// ---------------------------------------------------------------------------
// BN + GELU + MaxPool. One block per (c,b) plane.
// Padded smem plane (-inf halo) -> no bounds checks in the pool loop.
#define POOL_THREADS 256
#define SROWS 113                 // rows -1..111
#define SPITCH 120                // cols -1..111 at offset +4, 16B aligned
#define SPLANE (SROWS*SPITCH)     // 13560 floats = 54240 B

__global__ __launch_bounds__(POOL_THREADS)
void bn_gelu_pool_kernel(float* __restrict__ out) {
    extern __shared__ float sG[];
    const int c = blockIdx.x;
    const int b = blockIdx.y;
    const int tid = threadIdx.x;

    // fill with -inf (halo stays -inf; interior overwritten)
    float4 ninf = make_float4(-1e30f, -1e30f, -1e30f, -1e30f);
    float4* s4 = (float4*)sG;
    for (int i = tid; i < SPLANE/4; i += POOL_THREADS) s4[i] = ninf;
    __syncthreads();

    const float scale = g_scale[c];
    const float shift = g_shift[c];

    // phase 1: load fp16 y, BN + exact GELU, write into padded smem
    const float4* yv = (const float4*)(g_yh + (size_t)(b*CO + c)*(OH*OW));
    for (int i = tid; i < (OH*OW)/8; i += POOL_THREADS) {   // 1568 chunks of 8
        float4 p = yv[i];
        const __half2* h2 = (const __half2*)&p;
        int r = i / 14;                 // 14 chunks per row
        int cc = (i - r*14) * 8;
        float* dst = &sG[(r+1)*SPITCH + cc + 4];
        float v[8];
        #pragma unroll
        for (int j = 0; j < 4; ++j) {
            float2 f = __half22float2(h2[j]);
            v[2*j]   = fmaf(f.x, scale, shift);
            v[2*j+1] = fmaf(f.y, scale, shift);
        }
        #pragma unroll
        for (int j = 0; j < 8; ++j)
            v[j] = 0.5f*v[j]*(1.0f + erff(v[j]*0.70710678118654752f));
        *(float4*)(dst)     = make_float4(v[0], v[1], v[2], v[3]);
        *(float4*)(dst + 4) = make_float4(v[4], v[5], v[6], v[7]);
    }
    __syncthreads();

    // phase 2: 3x3 s2 max pool, no bounds checks
    float* op = &out[(size_t)(b*CO + c)*(PH*PW)];
    for (int i = tid; i < PH*PW; i += POOL_THREADS) {
        int py = i / PW;
        int px = i - py*PW;
        const float* p0 = &sG[(2*py)*SPITCH + 2*px + 3];
        const float* p1 = p0 + SPITCH;
        const float* p2 = p1 + SPITCH;
        float m = fmaxf(fmaxf(p0[0], p0[1]), p0[2]);
        m = fmaxf(m, fmaxf(fmaxf(p1[0], p1[1]), p1[2]));
        m = fmaxf(m, fmaxf(fmaxf(p2[0], p2[1]), p2[2]));
        op[i] = m;
    }
}

// ---------------------------------------------------------------------------
extern "C" void kernel_launch(void* const* d_in, const int* in_sizes, int n_in,
                              void* d_out, int out_size) {
    const float* x      = (const float*)d_in[0];
    const float* conv_w = (const float*)d_in[1];
    const float* conv_b = (const float*)d_in[2];
    const float* gamma  = (const float*)d_in[3];
    const float* beta   = (const float*)d_in[4];
    float* out = (float*)d_out;

    const int conv_smem = (SIN_SZ + SW_SZ) * sizeof(float);  // 33840 B
    const int pool_smem = SPLANE * sizeof(float);            // 54240 B
    cudaFuncSetAttribute(conv_stats_kernel,
                         cudaFuncAttributeMaxDynamicSharedMemorySize, conv_smem);
    cudaFuncSetAttribute(bn_gelu_pool_kernel,
                         cudaFuncAttributeMaxDynamicSharedMemorySize, pool_smem);

    zero_stats_kernel<<<1, CO>>>();
    conv_stats_kernel<<<dim3(28, B_, 3), CONV_THREADS, conv_smem>>>(x, conv_w, conv_b);
    finalize_stats_kernel<<<1, CO>>>(gamma, beta);
    bn_gelu_pool_kernel<<<dim3(CO, B_), POOL_THREADS, pool_smem>>>(out);
}

// round 3
// speedup vs baseline: 1.6156x; 1.0827x over previous
#include <cuda_runtime.h>
#include <cuda_fp16.h>
#include <math.h>

#define B_    32
#define CIN   3
#define HIN   224
#define WIN   224
#define CO    192
#define OH    112
#define OW    112
#define PH    56
#define PW    56
#define NPC   (B_*OH*OW)   // 401408

typedef unsigned long long u64;

// -------- device scratch ----------------------------------------------------
__device__ __half g_yh[(size_t)B_*CO*OH*OW];   // conv output fp16, ~154 MB
__device__ float g_sum[CO];
__device__ float g_sq[CO];
__device__ float g_scale[CO];
__device__ float g_shift[CO];

// -------- packed fp32x2 helpers (sm_103a FFMA2 path) ------------------------
__device__ __forceinline__ u64 pk2(float lo, float hi) {
    u64 r; asm("mov.b64 %0,{%1,%2};" : "=l"(r) : "f"(lo), "f"(hi)); return r;
}
__device__ __forceinline__ void upk2(u64 v, float& lo, float& hi) {
    asm("mov.b64 {%0,%1},%2;" : "=f"(lo), "=f"(hi) : "l"(v));
}
__device__ __forceinline__ void fma2(u64& d, u64 a, u64 b) {
    asm("fma.rn.f32x2 %0,%1,%2,%0;" : "+l"(d) : "l"(a), "l"(b));
}
__device__ __forceinline__ void add2(u64& d, u64 a) {
    asm("add.rn.f32x2 %0,%0,%1;" : "+l"(d) : "l"(a));
}

// ---------------------------------------------------------------------------
__global__ void zero_stats_kernel() {
    int t = threadIdx.x;
    if (t < CO) { g_sum[t] = 0.f; g_sq[t] = 0.f; }
}

// ---------------------------------------------------------------------------
// Conv + stats. Block: 256 thr = 8 warps; warp -> 8 channels (4 packed pairs),
// lane -> 2 output cols. Tile: 4 output rows. Weights hoisted per (ci,ky),
// FFMA2 over channel pairs.
#define CONV_THREADS 256
#define IN_ROWS  9
#define IN_COLS  132
#define SIN_SZ   (CIN*IN_ROWS*IN_COLS)   // 3564 floats
#define SW_SZ    (27*64)                 // 1728 floats

__global__ __launch_bounds__(CONV_THREADS, 2)
void conv_stats_kernel(const float* __restrict__ x,
                       const float* __restrict__ conv_w,
                       const float* __restrict__ conv_b) {
    extern __shared__ float smem[];
    float* sIn = smem;              // [ci][9][132]
    float* sW  = smem + SIN_SZ;     // [tap][ch_local 0..63]

    const int tid  = threadIdx.x;
    const int lane = tid & 31;
    const int wrp  = tid >> 5;

    const int ct = blockIdx.x & 1;       // col tile (0: 64 cols, 1: 48 cols)
    const int rt = blockIdx.x >> 1;      // 4-row tile, 0..27
    const int b  = blockIdx.y;
    const int cz = blockIdx.z;           // 64-channel group

    const int c0     = ct * 64;
    const bool active = (2*lane) < (ct ? 48 : 64);

    // ---- load input tile (zero padded) ----
    const int rowbase = 8*rt - 1;
    const int colbase = 2*c0 - 1;
    for (int idx = tid; idx < SIN_SZ; idx += CONV_THREADS) {
        int ci  = idx / (IN_ROWS*IN_COLS);
        int rem = idx - ci*(IN_ROWS*IN_COLS);
        int r   = rem / IN_COLS;
        int col = rem - r*IN_COLS;
        int gr = rowbase + r;
        int gc = colbase + col;
        float v = 0.f;
        if (gr >= 0 && gr < HIN && gc >= 0 && gc < WIN)
            v = x[((size_t)(b*CIN + ci)*HIN + gr)*WIN + gc];
        sIn[idx] = v;
    }
    for (int idx = tid; idx < SW_SZ; idx += CONV_THREADS) {
        int tap = idx >> 6;
        int cl  = idx & 63;
        sW[idx] = conv_w[(cz*64 + cl)*27 + tap];
    }
    __syncthreads();

    const int cbase = cz*64 + wrp*8;
    u64 bp[4];
    #pragma unroll
    for (int p = 0; p < 4; ++p)
        bp[p] = pk2(conv_b[cbase + 2*p], conv_b[cbase + 2*p + 1]);

    // acc[oy][col][pair]
    u64 acc[4][2][4];
    #pragma unroll
    for (int oy = 0; oy < 4; ++oy)
        #pragma unroll
        for (int q = 0; q < 2; ++q)
            #pragma unroll
            for (int p = 0; p < 4; ++p) acc[oy][q][p] = bp[p];

    const float4* sW4 = (const float4*)sW;

    #pragma unroll
    for (int ci = 0; ci < 3; ++ci) {
        #pragma unroll
        for (int ky = 0; ky < 3; ++ky) {
            // hoisted weights for 3 kx taps, 4 channel-pairs each
            u64 w0[4], w1[4], w2[4];
            {
                union { float4 f; u64 u[2]; } t;
                const int base = (ci*9 + ky*3)*16 + wrp*2;
                t.f = sW4[base+0];  w0[0]=t.u[0]; w0[1]=t.u[1];
                t.f = sW4[base+1];  w0[2]=t.u[0]; w0[3]=t.u[1];
                t.f = sW4[base+16]; w1[0]=t.u[0]; w1[1]=t.u[1];
                t.f = sW4[base+17]; w1[2]=t.u[0]; w1[3]=t.u[1];
                t.f = sW4[base+32]; w2[0]=t.u[0]; w2[1]=t.u[1];
                t.f = sW4[base+33]; w2[2]=t.u[0]; w2[3]=t.u[1];
            }
            const float* iprow = &sIn[ci*(IN_ROWS*IN_COLS) + ky*IN_COLS + 4*lane];
            #pragma unroll
            for (int oy = 0; oy < 4; ++oy) {
                const float* ip = iprow + oy*(2*IN_COLS);
                float4 a = *(const float4*)ip;
                float  e = ip[4];
                u64 sx = pk2(a.x, a.x);
                u64 sy = pk2(a.y, a.y);
                u64 sz = pk2(a.z, a.z);
                u64 sw = pk2(a.w, a.w);
                u64 se = pk2(e, e);
                #pragma unroll
                for (int p = 0; p < 4; ++p) {
                    fma2(acc[oy][0][p], w0[p], sx);   // kx=0, col0
                    fma2(acc[oy][1][p], w0[p], sz);   // kx=0, col1
                    fma2(acc[oy][0][p], w1[p], sy);   // kx=1, col0
                    fma2(acc[oy][1][p], w1[p], sw);   // kx=1, col1
                    fma2(acc[oy][0][p], w2[p], sz);   // kx=2, col0
                    fma2(acc[oy][1][p], w2[p], se);   // kx=2, col1
                }
            }
        }
    }

    // epilogue: stores + stats (packed)
    u64 ssum[4] = {0,0,0,0};
    u64 ssq [4] = {0,0,0,0};
    if (active) {
        #pragma unroll
        for (int oy = 0; oy < 4; ++oy) {
            const int OY = 4*rt + oy;
            #pragma unroll
            for (int p = 0; p < 4; ++p) {
                float v0lo, v0hi, v1lo, v1hi;
                upk2(acc[oy][0][p], v0lo, v0hi);   // col0: ch 2p / 2p+1
                upk2(acc[oy][1][p], v1lo, v1hi);   // col1
                __half2* d0 = (__half2*)(g_yh + ((size_t)(b*CO + cbase + 2*p    )*OH + OY)*OW);
                __half2* d1 = (__half2*)(g_yh + ((size_t)(b*CO + cbase + 2*p + 1)*OH + OY)*OW);
                d0[(c0>>1) + lane] = __floats2half2_rn(v0lo, v1lo);
                d1[(c0>>1) + lane] = __floats2half2_rn(v0hi, v1hi);
                add2(ssum[p], acc[oy][0][p]);
                add2(ssum[p], acc[oy][1][p]);
                fma2(ssq[p], acc[oy][0][p], acc[oy][0][p]);
                fma2(ssq[p], acc[oy][1][p], acc[oy][1][p]);
            }
        }
    }

    // warp reduce per channel, lane0 atomics
    #pragma unroll
    for (int p = 0; p < 4; ++p) {
        float slo, shi, qlo, qhi;
        upk2(ssum[p], slo, shi);
        upk2(ssq [p], qlo, qhi);
        #pragma unroll
        for (int o = 16; o > 0; o >>= 1) {
            slo += __shfl_xor_sync(0xffffffffu, slo, o);
            shi += __shfl_xor_sync(0xffffffffu, shi, o);
            qlo += __shfl_xor_sync(0xffffffffu, qlo, o);
            qhi += __shfl_xor_sync(0xffffffffu, qhi, o);
        }
        if (lane == 0) {
            atomicAdd(&g_sum[cbase + 2*p    ], slo);
            atomicAdd(&g_sum[cbase + 2*p + 1], shi);
            atomicAdd(&g_sq [cbase + 2*p    ], qlo);
            atomicAdd(&g_sq [cbase + 2*p + 1], qhi);
        }
    }
}

// ---------------------------------------------------------------------------
__global__ void finalize_stats_kernel(const float* __restrict__ gamma,
                                      const float* __restrict__ beta) {
    int c = threadIdx.x;
    if (c >= CO) return;
    float invN  = 1.0f / (float)NPC;
    float mean  = g_sum[c] * invN;
    float var   = g_sq[c] * invN - mean*mean;
    float inv   = rsqrtf(var + 1e-5f);
    float scale = gamma[c] * inv;
    g_scale[c]  = scale;
    g_shift[c]  = beta[c] - mean*scale;
}

// ---------------------------------------------------------------------------
// BN + GELU + MaxPool. One block per (c,b) plane, 224 threads.
// Interior stored at sG[(r+1)*SPITCH + cc + 4]; halo = top row + left col.
#define POOL_THREADS 224
#define SROWS 113
#define SPITCH 120
#define SPLANE (SROWS*SPITCH)

__global__ __launch_bounds__(POOL_THREADS)
void bn_gelu_pool_kernel(float* __restrict__ out) {
    extern __shared__ float sG[];
    const int c = blockIdx.x;
    const int b = blockIdx.y;
    const int tid = threadIdx.x;

    // halo: top row (120 cells) + left col (112 cells)
    const float NINF = -1e30f;
    if (tid < 120) sG[tid] = NINF;
    for (int i = tid; i < 112; i += POOL_THREADS) sG[(i+1)*SPITCH + 3] = NINF;

    const float scale = g_scale[c];
    const float shift = g_shift[c];

    // phase 1: BN + exact GELU into padded smem. 14 col-chunks x 16 rows.
    const int k  = tid % 14;          // col chunk: 8 floats
    const int r0 = tid / 14;          // row 0..15
    const float4* yv = (const float4*)(g_yh + (size_t)(b*CO + c)*(OH*OW));
    for (int r = r0; r < OH; r += 16) {
        float4 p = yv[r*14 + k];
        const __half2* h2 = (const __half2*)&p;
        float v[8];
        #pragma unroll
        for (int j = 0; j < 4; ++j) {
            float2 f = __half22float2(h2[j]);
            v[2*j]   = fmaf(f.x, scale, shift);
            v[2*j+1] = fmaf(f.y, scale, shift);
        }
        #pragma unroll
        for (int j = 0; j < 8; ++j)
            v[j] = 0.5f*v[j]*(1.0f + erff(v[j]*0.70710678118654752f));
        float* dst = &sG[(r+1)*SPITCH + 8*k + 4];
        *(float4*)(dst)     = make_float4(v[0], v[1], v[2], v[3]);
        *(float4*)(dst + 4) = make_float4(v[4], v[5], v[6], v[7]);
    }
    __syncthreads();

    // phase 2: 3x3 s2 maxpool, 4 outputs/thread, no bounds checks, no divs.
    const int g  = tid % 14;          // output col group: px = 4g..4g+3
    const int ty = tid / 14;          // row 0..15
    float* op = &out[(size_t)(b*CO + c)*(PH*PW)];
    for (int py = ty; py < PH; py += 16) {
        const float* r0p = &sG[(2*py)*SPITCH + 8*g + 3];
        const float* r1p = r0p + SPITCH;
        const float* r2p = r1p + SPITCH;
        float  s0 = r0p[0],                 s1 = r1p[0],                 s2 = r2p[0];
        float4 a0 = *(const float4*)(r0p+1), a1 = *(const float4*)(r1p+1), a2 = *(const float4*)(r2p+1);
        float4 b0 = *(const float4*)(r0p+5), b1 = *(const float4*)(r1p+5), b2 = *(const float4*)(r2p+5);
        // column-wise max of 3 rows -> m[0..8]
        float m0 = fmaxf(s0,   fmaxf(s1,   s2));
        float m1 = fmaxf(a0.x, fmaxf(a1.x, a2.x));
        float m2 = fmaxf(a0.y, fmaxf(a1.y, a2.y));
        float m3 = fmaxf(a0.z, fmaxf(a1.z, a2.z));
        float m4 = fmaxf(a0.w, fmaxf(a1.w, a2.w));
        float m5 = fmaxf(b0.x, fmaxf(b1.x, b2.x));
        float m6 = fmaxf(b0.y, fmaxf(b1.y, b2.y));
        float m7 = fmaxf(b0.z, fmaxf(b1.z, b2.z));
        float m8 = fmaxf(b0.w, fmaxf(b1.w, b2.w));
        float4 o;
        o.x = fmaxf(m0, fmaxf(m1, m2));
        o.y = fmaxf(m2, fmaxf(m3, m4));
        o.z = fmaxf(m4, fmaxf(m5, m6));
        o.w = fmaxf(m6, fmaxf(m7, m8));
        *(float4*)&op[py*PW + 4*g] = o;
    }
}

// ---------------------------------------------------------------------------
extern "C" void kernel_launch(void* const* d_in, const int* in_sizes, int n_in,
                              void* d_out, int out_size) {
    const float* x      = (const float*)d_in[0];
    const float* conv_w = (const float*)d_in[1];
    const float* conv_b = (const float*)d_in[2];
    const float* gamma  = (const float*)d_in[3];
    const float* beta   = (const float*)d_in[4];
    float* out = (float*)d_out;

    const int conv_smem = (SIN_SZ + SW_SZ) * sizeof(float);  // 21168 B
    const int pool_smem = SPLANE * sizeof(float);            // 54240 B
    cudaFuncSetAttribute(conv_stats_kernel,
                         cudaFuncAttributeMaxDynamicSharedMemorySize, conv_smem);
    cudaFuncSetAttribute(bn_gelu_pool_kernel,
                         cudaFuncAttributeMaxDynamicSharedMemorySize, pool_smem);

    zero_stats_kernel<<<1, CO>>>();
    conv_stats_kernel<<<dim3(56, B_, 3), CONV_THREADS, conv_smem>>>(x, conv_w, conv_b);
    finalize_stats_kernel<<<1, CO>>>(gamma, beta);
    bn_gelu_pool_kernel<<<dim3(CO, B_), POOL_THREADS, pool_smem>>>(out);
}

// round 4
// speedup vs baseline: 1.7832x; 1.1038x over previous
#include <cuda_runtime.h>
#include <cuda_fp16.h>
#include <math.h>

#define B_    32
#define CIN   3
#define HIN   224
#define WIN   224
#define CO    192
#define OH    112
#define OW    112
#define PH    56
#define PW    56
#define NPC   (B_*OH*OW)   // 401408

typedef unsigned long long u64;

// -------- device scratch ----------------------------------------------------
__device__ __half g_yh[(size_t)B_*CO*OH*OW];   // conv output fp16, ~154 MB
__device__ float g_sum[CO];
__device__ float g_sq[CO];
__device__ float g_scale[CO];
__device__ float g_shift[CO];

// -------- packed fp32x2 helpers ---------------------------------------------
__device__ __forceinline__ u64 pk2(float lo, float hi) {
    u64 r; asm("mov.b64 %0,{%1,%2};" : "=l"(r) : "f"(lo), "f"(hi)); return r;
}
__device__ __forceinline__ void upk2(u64 v, float& lo, float& hi) {
    asm("mov.b64 {%0,%1},%2;" : "=f"(lo), "=f"(hi) : "l"(v));
}
__device__ __forceinline__ void fma2(u64& d, u64 a, u64 b) {
    asm("fma.rn.f32x2 %0,%1,%2,%0;" : "+l"(d) : "l"(a), "l"(b));
}
__device__ __forceinline__ void add2(u64& d, u64 a) {
    asm("add.rn.f32x2 %0,%0,%1;" : "+l"(d) : "l"(a));
}

// ---------------------------------------------------------------------------
__global__ void zero_stats_kernel() {
    int t = threadIdx.x;
    if (t < CO) { g_sum[t] = 0.f; g_sq[t] = 0.f; }
}

// ---------------------------------------------------------------------------
// Conv + stats. 256 thr = 8 warps; warp -> 8 channels, processed as TWO
// sequential 4-channel halves (keeps acc = 16 u64 = 32 regs live -> no spill
// at 2 blocks/SM). Lane -> 2 output cols. Tile: 4 output rows.
// Inner loop walks the 9 INPUT rows once; each row feeds (oy,ky) pairs:
//   even r: (oy=r/2, ky=0) and (oy=r/2-1, ky=2);  odd r: (oy=(r-1)/2, ky=1).
#define CONV_THREADS 256
#define IN_ROWS  9
#define IN_COLS  132
#define SIN_SZ   (CIN*IN_ROWS*IN_COLS)   // 3564 floats
#define SW_SZ    (27*64)                 // 1728 floats

__global__ __launch_bounds__(CONV_THREADS, 2)
void conv_stats_kernel(const float* __restrict__ x,
                       const float* __restrict__ conv_w,
                       const float* __restrict__ conv_b) {
    extern __shared__ float smem[];
    float* sIn = smem;              // [ci][9][132]
    float* sW  = smem + SIN_SZ;     // [tap][ch_local 0..63]

    const int tid  = threadIdx.x;
    const int lane = tid & 31;
    const int wrp  = tid >> 5;

    const int ct = blockIdx.x & 1;       // col tile (0: 64 cols, 1: 48 cols)
    const int rt = blockIdx.x >> 1;      // 4-row tile, 0..27
    const int b  = blockIdx.y;
    const int cz = blockIdx.z;           // 64-channel group

    const int c0     = ct * 64;
    const bool active = (2*lane) < (ct ? 48 : 64);

    // ---- load input tile (zero padded) ----
    const int rowbase = 8*rt - 1;
    const int colbase = 2*c0 - 1;
    for (int idx = tid; idx < SIN_SZ; idx += CONV_THREADS) {
        int ci  = idx / (IN_ROWS*IN_COLS);
        int rem = idx - ci*(IN_ROWS*IN_COLS);
        int r   = rem / IN_COLS;
        int col = rem - r*IN_COLS;
        int gr = rowbase + r;
        int gc = colbase + col;
        float v = 0.f;
        if (gr >= 0 && gr < HIN && gc >= 0 && gc < WIN)
            v = x[((size_t)(b*CIN + ci)*HIN + gr)*WIN + gc];
        sIn[idx] = v;
    }
    for (int idx = tid; idx < SW_SZ; idx += CONV_THREADS) {
        int tap = idx >> 6;
        int cl  = idx & 63;
        sW[idx] = conv_w[(cz*64 + cl)*27 + tap];
    }
    __syncthreads();

    const float4* sW4 = (const float4*)sW;

    #pragma unroll 1
    for (int h = 0; h < 2; ++h) {        // channel half: ch cb..cb+3
        const int cb = cz*64 + wrp*8 + h*4;
        u64 bp0 = pk2(conv_b[cb+0], conv_b[cb+1]);
        u64 bp1 = pk2(conv_b[cb+2], conv_b[cb+3]);

        u64 acc[4][2][2];                 // [oy][col][pair]
        #pragma unroll
        for (int oy = 0; oy < 4; ++oy) {
            acc[oy][0][0] = bp0; acc[oy][1][0] = bp0;
            acc[oy][0][1] = bp1; acc[oy][1][1] = bp1;
        }

        #pragma unroll
        for (int ci = 0; ci < 3; ++ci) {
            // weights for this ci & half: t[ky][kx] -> 2 pairs each
            union { float4 f; u64 u[2]; } t[3][3];
            #pragma unroll
            for (int ky = 0; ky < 3; ++ky)
                #pragma unroll
                for (int kx = 0; kx < 3; ++kx)
                    t[ky][kx].f = sW4[(ci*9 + ky*3 + kx)*16 + wrp*2 + h];

            const float* iprow = &sIn[ci*(IN_ROWS*IN_COLS) + 4*lane];
            #pragma unroll
            for (int r = 0; r < 9; ++r) {
                const float* ip = iprow + r*IN_COLS;
                float4 a = *(const float4*)ip;
                float e = __shfl_down_sync(0xffffffffu, a.x, 1);
                if (lane == 31) e = ip[4];
                u64 sx = pk2(a.x, a.x);
                u64 sy = pk2(a.y, a.y);
                u64 sz = pk2(a.z, a.z);
                u64 sw = pk2(a.w, a.w);
                u64 se = pk2(e, e);
                // apply to (oy,ky) pairs this row feeds
                #pragma unroll
                for (int ky = 0; ky < 3; ++ky) {
                    if (((r - ky) & 1) != 0) continue;   // parity
                    const int oy = (r - ky) >> 1;
                    if (oy < 0 || oy >= 4) continue;
                    #pragma unroll
                    for (int p = 0; p < 2; ++p) {
                        fma2(acc[oy][0][p], t[ky][0].u[p], sx);
                        fma2(acc[oy][1][p], t[ky][0].u[p], sz);
                        fma2(acc[oy][0][p], t[ky][1].u[p], sy);
                        fma2(acc[oy][1][p], t[ky][1].u[p], sw);
                        fma2(acc[oy][0][p], t[ky][2].u[p], sz);
                        fma2(acc[oy][1][p], t[ky][2].u[p], se);
                    }
                }
            }
        }

        // epilogue for this half
        u64 ssum[2] = {0,0};
        u64 ssq [2] = {0,0};
        if (active) {
            #pragma unroll
            for (int oy = 0; oy < 4; ++oy) {
                const int OY = 4*rt + oy;
                #pragma unroll
                for (int p = 0; p < 2; ++p) {
                    float v0lo, v0hi, v1lo, v1hi;
                    upk2(acc[oy][0][p], v0lo, v0hi);
                    upk2(acc[oy][1][p], v1lo, v1hi);
                    __half2* d0 = (__half2*)(g_yh + ((size_t)(b*CO + cb + 2*p    )*OH + OY)*OW);
                    __half2* d1 = (__half2*)(g_yh + ((size_t)(b*CO + cb + 2*p + 1)*OH + OY)*OW);
                    d0[(c0>>1) + lane] = __floats2half2_rn(v0lo, v1lo);
                    d1[(c0>>1) + lane] = __floats2half2_rn(v0hi, v1hi);
                    add2(ssum[p], acc[oy][0][p]);
                    add2(ssum[p], acc[oy][1][p]);
                    fma2(ssq[p], acc[oy][0][p], acc[oy][0][p]);
                    fma2(ssq[p], acc[oy][1][p], acc[oy][1][p]);
                }
            }
        }
        #pragma unroll
        for (int p = 0; p < 2; ++p) {
            float slo, shi, qlo, qhi;
            upk2(ssum[p], slo, shi);
            upk2(ssq [p], qlo, qhi);
            #pragma unroll
            for (int o = 16; o > 0; o >>= 1) {
                slo += __shfl_xor_sync(0xffffffffu, slo, o);
                shi += __shfl_xor_sync(0xffffffffu, shi, o);
                qlo += __shfl_xor_sync(0xffffffffu, qlo, o);
                qhi += __shfl_xor_sync(0xffffffffu, qhi, o);
            }
            if (lane == 0) {
                atomicAdd(&g_sum[cb + 2*p    ], slo);
                atomicAdd(&g_sum[cb + 2*p + 1], shi);
                atomicAdd(&g_sq [cb + 2*p    ], qlo);
                atomicAdd(&g_sq [cb + 2*p + 1], qhi);
            }
        }
    }
}

// ---------------------------------------------------------------------------
__global__ void finalize_stats_kernel(const float* __restrict__ gamma,
                                      const float* __restrict__ beta) {
    int c = threadIdx.x;
    if (c >= CO) return;
    float invN  = 1.0f / (float)NPC;
    float mean  = g_sum[c] * invN;
    float var   = g_sq[c] * invN - mean*mean;
    float inv   = rsqrtf(var + 1e-5f);
    float scale = gamma[c] * inv;
    g_scale[c]  = scale;
    g_shift[c]  = beta[c] - mean*scale;
}

// ---------------------------------------------------------------------------
// BN + GELU + MaxPool via unimodality: max_w gelu(affine(y)) over a window
// = max(gelu(affine(min_w y)), gelu(affine(max_w y))).
// smem holds RAW fp16 y with NaN halo (hmin/hmax ignore NaN). Only 2 erf
// evals per OUTPUT (56x56) instead of 1 per input (112x112).
#define POOL_THREADS 224
#define PPITCH 136                // halves; interior col c at idx c+8
#define PROWS  113                // rows -1..111
#define PPLANE (PROWS*PPITCH)     // 15368 halves = 30736 B

__global__ __launch_bounds__(POOL_THREADS)
void bn_gelu_pool_kernel(float* __restrict__ out) {
    extern __shared__ __half sH[];
    const int c = blockIdx.x;
    const int b = blockIdx.y;
    const int tid = threadIdx.x;

    const __half NH = __ushort_as_half((unsigned short)0x7e00);  // NaN
    if (tid < PPITCH) sH[tid] = NH;                   // top halo row
    for (int i = tid; i < OH; i += POOL_THREADS)      // left halo col
        sH[(i+1)*PPITCH + 7] = NH;

    // phase 1: raw copy gmem fp16 -> padded smem (float4 = 8 halves)
    const int k  = tid % 14;
    const int r0 = tid / 14;
    const float4* yv = (const float4*)(g_yh + (size_t)(b*CO + c)*(OH*OW));
    for (int r = r0; r < OH; r += 16) {
        float4 p = yv[r*14 + k];
        *(float4*)&sH[(r+1)*PPITCH + 8 + 8*k] = p;
    }
    __syncthreads();

    const float scale = g_scale[c];
    const float shift = g_shift[c];

    // phase 2: per 4 outputs: column min/max over 3 rows, window min/max,
    // then 2 gelu evals per output.
    const int g  = tid % 14;          // px group: 4g..4g+3 -> cols 8g-1..8g+7
    const int ty = tid / 14;
    float* op = &out[(size_t)(b*CO + c)*(PH*PW)];
    for (int py = ty; py < PH; py += 16) {
        const __half* q0 = &sH[(2*py)*PPITCH + 8*g + 7];
        const __half* q1 = q0 + PPITCH;
        const __half* q2 = q1 + PPITCH;
        __half cm[9], cM[9];
        #pragma unroll
        for (int j = 0; j < 9; ++j) {
            __half a = q0[j], bb = q1[j], cc = q2[j];
            cM[j] = __hmax(__hmax(a, bb), cc);
            cm[j] = __hmin(__hmin(a, bb), cc);
        }
        float4 o;
        float* ov = (float*)&o;
        #pragma unroll
        for (int j = 0; j < 4; ++j) {
            __half wm = __hmin(__hmin(cm[2*j], cm[2*j+1]), cm[2*j+2]);
            __half wM = __hmax(__hmax(cM[2*j], cM[2*j+1]), cM[2*j+2]);
            float a1 = fmaf(__half2float(wm), scale, shift);
            float a2 = fmaf(__half2float(wM), scale, shift);
            float g1 = 0.5f*a1*(1.0f + erff(a1*0.70710678118654752f));
            float g2 = 0.5f*a2*(1.0f + erff(a2*0.70710678118654752f));
            ov[j] = fmaxf(g1, g2);
        }
        *(float4*)&op[py*PW + 4*g] = o;
    }
}

// ---------------------------------------------------------------------------
extern "C" void kernel_launch(void* const* d_in, const int* in_sizes, int n_in,
                              void* d_out, int out_size) {
    const float* x      = (const float*)d_in[0];
    const float* conv_w = (const float*)d_in[1];
    const float* conv_b = (const float*)d_in[2];
    const float* gamma  = (const float*)d_in[3];
    const float* beta   = (const float*)d_in[4];
    float* out = (float*)d_out;

    const int conv_smem = (SIN_SZ + SW_SZ) * sizeof(float);  // 21168 B
    const int pool_smem = PPLANE * sizeof(__half);           // 30736 B
    cudaFuncSetAttribute(conv_stats_kernel,
                         cudaFuncAttributeMaxDynamicSharedMemorySize, conv_smem);
    cudaFuncSetAttribute(bn_gelu_pool_kernel,
                         cudaFuncAttributeMaxDynamicSharedMemorySize, pool_smem);

    zero_stats_kernel<<<1, CO>>>();
    conv_stats_kernel<<<dim3(56, B_, 3), CONV_THREADS, conv_smem>>>(x, conv_w, conv_b);
    finalize_stats_kernel<<<1, CO>>>(gamma, beta);
    bn_gelu_pool_kernel<<<dim3(CO, B_), POOL_THREADS, pool_smem>>>(out);
}